// round 1
// baseline (speedup 1.0000x reference)
#include <cuda_runtime.h>
#include <cstdint>
#include <cstddef>

#define TSTEPS 32
#define INF    27
#define HID    10

// ---------- packed f32x2 helpers (Blackwell) ----------
__device__ __forceinline__ unsigned long long pk2(float a, float b){
  unsigned long long r;
  asm("mov.b64 %0, {%1, %2};" : "=l"(r) : "f"(a), "f"(b));
  return r;
}
__device__ __forceinline__ float2 unpk2(unsigned long long v){
  float2 r;
  asm("mov.b64 {%0, %1}, %2;" : "=f"(r.x), "=f"(r.y) : "l"(v));
  return r;
}
__device__ __forceinline__ unsigned long long ffma2(unsigned long long a, unsigned long long b, unsigned long long c){
  unsigned long long d;
  asm("fma.rn.f32x2 %0, %1, %2, %3;" : "=l"(d) : "l"(a), "l"(b), "l"(c));
  return d;
}
__device__ __forceinline__ void cp8(uint32_t saddr, const void* gptr){
  asm volatile("cp.async.ca.shared.global [%0], [%1], 8;" :: "r"(saddr), "l"(gptr));
}
// sigmoid / tanh via MUFU.EX2 + MUFU.RCP (near-full precision)
__device__ __forceinline__ float sigf(float v){
  return __fdividef(1.f, 1.f + __expf(-v));
}
__device__ __forceinline__ float tanhfast(float v){
  return __fdividef(2.f, 1.f + __expf(-2.f*v)) - 1.f;
}

// Block: 64 threads, each thread owns 2 batch elements (packed f32x2) -> 128 elems/block.
__global__ void __launch_bounds__(64) lstm_fused_kernel(
    const float* __restrict__ word,
    const float* __restrict__ W_ih, const float* __restrict__ W_hh,
    const float* __restrict__ b_ih, const float* __restrict__ b_hh,
    const float* __restrict__ W_fc, const float* __restrict__ b_fc,
    const float* __restrict__ W_out, const float* __restrict__ b_out,
    float* __restrict__ out, int Bn)
{
  // weights pre-duplicated (w,w) as u64 so LDS.128 yields 2 FFMA2 operands
  __shared__ __align__(16) unsigned long long s_wih[40*28]; // rows padded 27->28, pad=0
  __shared__ __align__(16) unsigned long long s_whh[40*12]; // rows padded 10->12, pad=0
  __shared__ __align__(16) unsigned long long s_b[40];      // b_ih+b_hh, duplicated
  __shared__ float s_wfc[50], s_bfc[5], s_wout[5], s_bout[1];
  __shared__ __align__(16) float s_x[2][128*INF];           // double-buffered x staging

  const int tid = threadIdx.x;

  for (int idx = tid; idx < 40*28; idx += 64){
    int r = idx / 28, j = idx - r*28;
    float w = (j < 27) ? W_ih[r*27 + j] : 0.f;
    s_wih[idx] = pk2(w, w);
  }
  for (int idx = tid; idx < 40*12; idx += 64){
    int r = idx / 12, j = idx - r*12;
    float w = (j < 10) ? W_hh[r*10 + j] : 0.f;
    s_whh[idx] = pk2(w, w);
  }
  if (tid < 40){ float b = b_ih[tid] + b_hh[tid]; s_b[tid] = pk2(b, b); }
  if (tid < 50) s_wfc[tid] = W_fc[tid];
  if (tid < 5) { s_bfc[tid] = b_fc[tid]; s_wout[tid] = W_out[tid]; }
  if (tid == 0) s_bout[0] = b_out[0];

  const int blockElem = blockIdx.x * 128;
  const uint32_t sx0 = (uint32_t)__cvta_generic_to_shared(&s_x[0][0]);

  // stage t=0 into buffer 0
  {
    const float2* src = (const float2*)(word + ((size_t)blockElem) * INF);
    #pragma unroll
    for (int m = 0; m < 27; m++){
      int i2 = m*64 + tid;                 // 1728 float2 per block-step
      cp8(sx0 + (uint32_t)(i2*8), src + i2);
    }
    asm volatile("cp.async.commit_group;");
  }

  // packed recurrent state
  unsigned long long hp[12], hn[10];       // h padded to 12 (pads = 0)
  float c0a[10], c1a[10];
  #pragma unroll
  for (int k = 0; k < 12; k++) hp[k] = 0ull;
  #pragma unroll
  for (int k = 0; k < 10; k++){ c0a[k] = 0.f; c1a[k] = 0.f; }

  const int e0 = 2*tid;

  #pragma unroll 1
  for (int t = 0; t < TSTEPS; t++){
    if (t + 1 < TSTEPS){
      const float2* src = (const float2*)(word + ((size_t)(t+1)*Bn + blockElem) * INF);
      uint32_t dst = sx0 + (uint32_t)(((t+1)&1) * (128*INF*4));
      #pragma unroll
      for (int m = 0; m < 27; m++){
        int i2 = m*64 + tid;
        cp8(dst + (uint32_t)(i2*8), src + i2);
      }
      asm volatile("cp.async.commit_group;");
      asm volatile("cp.async.wait_group 1;");  // buffer for step t is done
    } else {
      asm volatile("cp.async.wait_group 0;");
    }
    __syncthreads();

    // pack this thread's 2 elements' x into registers
    const float* xb = &s_x[t & 1][0];
    unsigned long long xj[28];
    #pragma unroll
    for (int j = 0; j < 27; j++)
      xj[j] = pk2(xb[e0*INF + j], xb[e0*INF + INF + j]);
    xj[27] = 0ull;

    #pragma unroll
    for (int k = 0; k < 10; k++){
      unsigned long long ai = s_b[k], af = s_b[k+10], ag = s_b[k+20], ao = s_b[k+30];
      const ulonglong2* wi = (const ulonglong2*)(s_wih + (k     )*28);
      const ulonglong2* wf = (const ulonglong2*)(s_wih + (k + 10)*28);
      const ulonglong2* wg = (const ulonglong2*)(s_wih + (k + 20)*28);
      const ulonglong2* wo = (const ulonglong2*)(s_wih + (k + 30)*28);
      #pragma unroll
      for (int m = 0; m < 14; m++){
        ulonglong2 vi = wi[m], vf = wf[m], vg = wg[m], vo = wo[m];
        ai = ffma2(vi.x, xj[2*m], ai); ai = ffma2(vi.y, xj[2*m+1], ai);
        af = ffma2(vf.x, xj[2*m], af); af = ffma2(vf.y, xj[2*m+1], af);
        ag = ffma2(vg.x, xj[2*m], ag); ag = ffma2(vg.y, xj[2*m+1], ag);
        ao = ffma2(vo.x, xj[2*m], ao); ao = ffma2(vo.y, xj[2*m+1], ao);
      }
      const ulonglong2* ui = (const ulonglong2*)(s_whh + (k     )*12);
      const ulonglong2* uf = (const ulonglong2*)(s_whh + (k + 10)*12);
      const ulonglong2* ug = (const ulonglong2*)(s_whh + (k + 20)*12);
      const ulonglong2* uo = (const ulonglong2*)(s_whh + (k + 30)*12);
      #pragma unroll
      for (int m = 0; m < 6; m++){
        ulonglong2 vi = ui[m], vf = uf[m], vg = ug[m], vo = uo[m];
        ai = ffma2(vi.x, hp[2*m], ai); ai = ffma2(vi.y, hp[2*m+1], ai);
        af = ffma2(vf.x, hp[2*m], af); af = ffma2(vf.y, hp[2*m+1], af);
        ag = ffma2(vg.x, hp[2*m], ag); ag = ffma2(vg.y, hp[2*m+1], ag);
        ao = ffma2(vo.x, hp[2*m], ao); ao = ffma2(vo.y, hp[2*m+1], ao);
      }
      float2 gi = unpk2(ai), gf = unpk2(af), gg = unpk2(ag), go = unpk2(ao);
      float i0 = sigf(gi.x), i1 = sigf(gi.y);
      float f0 = sigf(gf.x), f1 = sigf(gf.y);
      float g0 = tanhfast(gg.x), g1 = tanhfast(gg.y);
      float o0 = sigf(go.x), o1 = sigf(go.y);
      float cn0 = fmaf(f0, c0a[k], i0*g0);
      float cn1 = fmaf(f1, c1a[k], i1*g1);
      float h0  = o0 * tanhfast(cn0);
      float h1  = o1 * tanhfast(cn1);
      c0a[k] = fmaxf(cn0, 0.f);             // ReLU on carried cell state
      c1a[k] = fmaxf(cn1, 0.f);
      hn[k]  = pk2(fmaxf(h0, 0.f), fmaxf(h1, 0.f)); // ReLU on carried hidden
    }
    #pragma unroll
    for (int k = 0; k < 10; k++) hp[k] = hn[k];
    __syncthreads();   // all reads of this buffer done before it is re-staged
  }

  // ---- head: FC(10->5) -> ReLU -> Linear(5->1) -> sigmoid ----
  float h0s[10], h1s[10];
  #pragma unroll
  for (int k = 0; k < 10; k++){ float2 v = unpk2(hp[k]); h0s[k] = v.x; h1s[k] = v.y; }
  float z0 = s_bout[0], z1 = s_bout[0];
  #pragma unroll
  for (int u = 0; u < 5; u++){
    float y0 = s_bfc[u], y1 = s_bfc[u];
    #pragma unroll
    for (int k = 0; k < 10; k++){
      y0 = fmaf(s_wfc[u*10 + k], h0s[k], y0);
      y1 = fmaf(s_wfc[u*10 + k], h1s[k], y1);
    }
    y0 = fmaxf(y0, 0.f); y1 = fmaxf(y1, 0.f);
    z0 = fmaf(s_wout[u], y0, z0);
    z1 = fmaf(s_wout[u], y1, z1);
  }
  const int b0 = blockElem + e0;
  if (b0     < Bn) out[b0]     = sigf(z0);
  if (b0 + 1 < Bn) out[b0 + 1] = sigf(z1);
}

extern "C" void kernel_launch(void* const* d_in, const int* in_sizes, int n_in,
                              void* d_out, int out_size) {
  const float* word  = (const float*)d_in[0];
  const float* W_ih  = (const float*)d_in[1];
  const float* W_hh  = (const float*)d_in[2];
  const float* b_ih  = (const float*)d_in[3];
  const float* b_hh  = (const float*)d_in[4];
  const float* W_fc  = (const float*)d_in[5];
  const float* b_fc  = (const float*)d_in[6];
  const float* W_out = (const float*)d_in[7];
  const float* b_out = (const float*)d_in[8];
  float* out = (float*)d_out;

  const int Bn = in_sizes[0] / (TSTEPS * INF);   // 65536
  const int blocks = (Bn + 127) / 128;           // 512 blocks of 64 threads

  lstm_fused_kernel<<<blocks, 64>>>(word, W_ih, W_hh, b_ih, b_hh,
                                    W_fc, b_fc, W_out, b_out, out, Bn);
}